// round 11
// baseline (speedup 1.0000x reference)
#include <cuda_runtime.h>

// Local 5x5 variance, reflect padding. float32 [16,3,1024,1024] -> same.
//
// Persistent-CTA continuous pipeline:
//   444 CTAs (148 SMs x 3 resident). 3072 tiles of 64(w) x 256(h); CTA b
//   owns tiles b, b+444, ... Each tile = 2 stages of 128 rows; the
//   double-buffered cp.async pipeline carries ACROSS tiles, so every
//   compute phase (except the last) has a load in flight and the pipeline
//   never drains at wave boundaries. Imbalance: 7 vs 6.92 tiles ~= 1.2%.
//   Per stage: 132x72 float halo tile in dynamic smem (37.1KB x 2 buffers).
//   Thread owns 4 cols x 8 rows (1.5x vertical-halo rowsum redundancy).

#define IMG 1024
#define NPLANES 48
#define TW 64
#define STAGE_H 128
#define STAGES 2                 // stages per tile (256 rows)
#define SROWS 132                // STAGE_H + 4 halo
#define SC4 18                   // 18 float4 = 72 floats per smem row
#define SBUF_ELEMS (SROWS * SC4)
#define SMEM_BYTES (2 * SBUF_ELEMS * 16)   // 76032 B -> 3 CTAs/SM
#define THREADS 256
#define NCTAS 444                // 148 * 3
#define NTILES 3072              // 16 x-tiles * 4 y-strips * 48 planes

__device__ __forceinline__ int reflect_idx(int i, int n) {
    if (i < 0) i = -i;
    if (i >= n) i = 2 * (n - 1) - i;
    return i;
}

__device__ __forceinline__ void cp_async16(void* smem_dst, const void* gsrc) {
    unsigned sa = (unsigned)__cvta_generic_to_shared(smem_dst);
    asm volatile("cp.async.cg.shared.global [%0], [%1], 16;\n" :: "r"(sa), "l"(gsrc));
}

// Horizontal 5-sums of x and x^2 for 4 output columns (floats 2..9 of a|b|c).
__device__ __forceinline__ void rowsum(float4 a, float4 b, float4 c,
                                       float* __restrict__ hh,
                                       float* __restrict__ hh2) {
    float x0 = a.z, x1 = a.w, x2 = b.x, x3 = b.y;
    float x4 = b.z, x5 = b.w, x6 = c.x, x7 = c.y;

    float h0 = x0 + x1 + x2 + x3 + x4;
    hh[0] = h0;
    hh[1] = h0    - x0 + x5;
    hh[2] = hh[1] - x1 + x6;
    hh[3] = hh[2] - x2 + x7;

    float q0 = x0 * x0, q1 = x1 * x1, q2 = x2 * x2, q3 = x3 * x3;
    float q4 = x4 * x4, q5 = x5 * x5, q6 = x6 * x6, q7 = x7 * x7;
    float g0 = q0 + q1 + q2 + q3 + q4;
    hh2[0] = g0;
    hh2[1] = g0     - q0 + q5;
    hh2[2] = hh2[1] - q1 + q6;
    hh2[3] = hh2[2] - q2 + q7;
}

__global__ __launch_bounds__(THREADS, 3)
void locvar5_kernel(const float* __restrict__ in, float* __restrict__ out) {
    extern __shared__ float4 sbuf[];   // 2 buffers of SBUF_ELEMS

    const int bid = blockIdx.x;
    const int tid = threadIdx.x;

    const int nTiles = (NTILES - bid + NCTAS - 1) / NCTAS;   // 6 or 7
    const int nVS = nTiles * STAGES;

    const int tx4 = tid & 15;
    const int ty  = tid >> 4;           // 16 strips of 8 rows

    const int rowInit = tid / SC4;      // one div/mod total
    const int c4Init  = tid - rowInit * SC4;

    // ---- stage loader: decode virtual stage -> (tile, stage), async copy ----
    auto load_stage = [&](int vs, int buf) {
        const int t  = bid + (vs >> 1) * NCTAS;
        const int s  = vs & 1;
        const int bx = (t & 15) * TW;
        const int by = ((t >> 4) & 3) * (STAGES * STAGE_H) + s * STAGE_H;
        const float* __restrict__ src = in + (size_t)(t >> 6) * IMG * IMG;
        const bool colEdge = (bx == 0) || (bx + TW == IMG);

        float4* sb = sbuf + buf * SBUF_ELEMS;
        const int r0 = by - 2;
        const bool rowsInterior = (r0 >= 0) && (r0 + SROWS <= IMG);
        int row = rowInit;
        int c4  = c4Init;
        while (row < SROWS) {
            const int gy = rowsInterior ? (r0 + row) : reflect_idx(r0 + row, IMG);
            const int gx = bx - 4 + c4 * 4;
            float4* sdst = sb + row * SC4 + c4;
            if (!colEdge || (c4 >= 1 && c4 <= 16)) {
                cp_async16(sdst, src + (size_t)gy * IMG + gx);
            } else {
                float4 v;
                v.x = src[(size_t)gy * IMG + reflect_idx(gx + 0, IMG)];
                v.y = src[(size_t)gy * IMG + reflect_idx(gx + 1, IMG)];
                v.z = src[(size_t)gy * IMG + reflect_idx(gx + 2, IMG)];
                v.w = src[(size_t)gy * IMG + reflect_idx(gx + 3, IMG)];
                *sdst = v;
            }
            // advance by 256 items: 256 = 14*18 + 4
            c4 += 4; row += 14;
            if (c4 >= SC4) { c4 -= SC4; ++row; }
        }
        asm volatile("cp.async.commit_group;\n" ::: "memory");
    };

    // ---- prologue ----
    load_stage(0, 0);
    asm volatile("cp.async.wait_group 0;\n" ::: "memory");
    __syncthreads();

    const float inv_n = 1.0f / 25.0f;

    for (int vs = 0; vs < nVS; ++vs) {
        if (vs + 1 < nVS) load_stage(vs + 1, (vs + 1) & 1);

        // ---- compute virtual stage vs from sbuf[vs&1] ----
        const int t  = bid + (vs >> 1) * NCTAS;
        const int s  = vs & 1;
        const int bx = (t & 15) * TW;
        const int by = ((t >> 4) & 3) * (STAGES * STAGE_H) + s * STAGE_H;
        float* __restrict__ dst = out + (size_t)(t >> 6) * IMG * IMG;

        const float4* sp = sbuf + (vs & 1) * SBUF_ELEMS + (ty * 8) * SC4 + tx4;

        float h[5][4], h2[5][4];
        #pragma unroll
        for (int j = 0; j < 4; ++j)
            rowsum(sp[j * SC4], sp[j * SC4 + 1], sp[j * SC4 + 2], h[j], h2[j]);

        float4* op = (float4*)(dst + (size_t)(by + ty * 8) * IMG + bx + tx4 * 4);
        #pragma unroll
        for (int j = 4; j < 12; ++j) {
            rowsum(sp[j * SC4], sp[j * SC4 + 1], sp[j * SC4 + 2],
                   h[j % 5], h2[j % 5]);
            float4 o;
            float* po = (float*)&o;
            #pragma unroll
            for (int cc = 0; cc < 4; ++cc) {
                const float S = h[0][cc] + h[1][cc] + h[2][cc] + h[3][cc] + h[4][cc];
                const float T = h2[0][cc] + h2[1][cc] + h2[2][cc] + h2[3][cc] + h2[4][cc];
                const float m = S * inv_n;
                po[cc] = fmaf(-m, m, T * inv_n);
            }
            *op = o;
            op += IMG / 4;
        }

        asm volatile("cp.async.wait_group 0;\n" ::: "memory");
        __syncthreads();
    }
}

extern "C" void kernel_launch(void* const* d_in, const int* in_sizes, int n_in,
                              void* d_out, int out_size) {
    const float* in = (const float*)d_in[0];
    float* out = (float*)d_out;
    cudaFuncSetAttribute(locvar5_kernel,
                         cudaFuncAttributeMaxDynamicSharedMemorySize, SMEM_BYTES);
    locvar5_kernel<<<NCTAS, THREADS, SMEM_BYTES>>>(in, out);
}